// round 14
// baseline (speedup 1.0000x reference)
#include <cuda_runtime.h>
#include <cuda_fp16.h>
#include <math.h>
#include <stdint.h>

// ---------------- problem constants ----------------
#define BATCH   2
#define L_SEQ   512
#define DM      768
#define DI      1536
#define NSTATE  16
#define RRANK   48
#define KCONV   4
#define NLAYER  4
#define VOCAB   50280
#define M_ROWS  (BATCH * L_SEQ)        // 1024
#define PROJ_N  (RRANK + 2 * NSTATE)   // 80

// ---------------- scratch (device globals) ----------------
__device__ float g_h   [M_ROWS * DM];
__device__ float g_xz  [M_ROWS * 2 * DI];
__device__ float g_proj[M_ROWS * PROJ_N];
__device__ float g_dt  [M_ROWS * DI];
__device__ __half g_r_h [M_ROWS * DM];
__device__ __half g_xc_h[M_ROWS * DI];
__device__ __half g_y_h [M_ROWS * DI];
__device__ __half g_emb_h [VOCAB * DM];
__device__ __half g_inw_h [NLAYER * 2 * DI * DM];
__device__ __half g_xw_h  [NLAYER * PROJ_N * DI];
__device__ __half g_outw_h[NLAYER * DM * DI];

// ---------------- PTX helpers (family-common) ----------------
__device__ __forceinline__ uint32_t smem_u32(const void* p) {
    uint32_t a;
    asm("{ .reg .u64 t; cvta.to.shared.u64 t, %1; cvt.u32.u64 %0, t; }"
        : "=r"(a) : "l"(p));
    return a;
}
__device__ __forceinline__ void ldsm4(uint32_t* r, uint32_t addr) {
    asm volatile("ldmatrix.sync.aligned.m8n8.x4.shared.b16 {%0,%1,%2,%3}, [%4];"
        : "=r"(r[0]), "=r"(r[1]), "=r"(r[2]), "=r"(r[3]) : "r"(addr));
}
__device__ __forceinline__ void mma_16n8k16(float* d, const uint32_t* a,
                                            uint32_t b0, uint32_t b1) {
    asm volatile(
        "mma.sync.aligned.m16n8k16.row.col.f32.f16.f16.f32 "
        "{%0,%1,%2,%3}, {%4,%5,%6,%7}, {%8,%9}, {%0,%1,%2,%3};"
        : "+f"(d[0]), "+f"(d[1]), "+f"(d[2]), "+f"(d[3])
        : "r"(a[0]), "r"(a[1]), "r"(a[2]), "r"(a[3]), "r"(b0), "r"(b1));
}
#define CP_ASYNC16(dst, src) \
    asm volatile("cp.async.cg.shared.global [%0], [%1], 16;" :: "r"(dst), "l"(src))
#define CP_COMMIT() asm volatile("cp.async.commit_group;" ::: "memory")
#define CP_WAIT1()  asm volatile("cp.async.wait_group 1;" ::: "memory")

// ======== fp16 mma.sync GEMM NT: C[M,N] (op)= A[M,K] * B[N,K]^T, fp32 accum ==
// Block tile 128x128, BK=32 halfs, 256 threads (8 warps, 2M x 4N, warp 64x32).
// 3-stage cp.async; forced 3 CTAs/SM (launch_bounds minBlocks=3, regs<=85).
// Inner loop B-first to minimize live registers.
// M % 128 == 0, Klen % 32 == 0. blockIdx.z = K-split. MODE: 0 store, 2 atomicAdd.
#define HSTRIDE 40
#define HTILE_HALFS (128 * HSTRIDE)          // 5120 halfs per matrix tile
#define STAGE_BH (2 * HTILE_HALFS * 2)       // 20480 B per stage
#define NSTAGE  3
#define HMMA_SMEM (NSTAGE * STAGE_BH)        // 61440 B

template <int MODE>
__global__ void __launch_bounds__(256, 3)
h16_gemm_nt(const __half* __restrict__ A, const __half* __restrict__ B,
            float* __restrict__ C, int N, int Klen, int lda, int ldb, int ldc) {
    extern __shared__ uint32_t smem[];
    const int tid = threadIdx.x;
    const int wid = tid >> 5;
    const int lane = tid & 31;
    const int g = lane >> 2;
    const int t = lane & 3;
    const int wm = wid & 1;      // warp M index (2) -> 64 rows
    const int wn = wid >> 1;     // warp N index (4) -> 32 cols
    const int bm = blockIdx.x * 128;
    const int bn = blockIdx.y * 128;
    const int kbase = blockIdx.z * Klen;

    const uint32_t sbase = smem_u32(smem);

    // per-lane ldmatrix offsets (bytes from stage base)
    const int j8  = lane & 7;
    const int sel = lane >> 3;
    uint32_t aoff[4], boff[2];
    #pragma unroll
    for (int fm = 0; fm < 4; fm++) {
        int row = wm * 64 + fm * 16 + j8 + ((sel & 1) << 3);
        aoff[fm] = (uint32_t)(row * 80 + ((sel & 2) ? 16 : 0));
    }
    #pragma unroll
    for (int p = 0; p < 2; p++) {
        int row = wn * 32 + p * 16 + j8 + ((sel & 2) ? 8 : 0);
        boff[p] = (uint32_t)(HTILE_HALFS * 2 + row * 80 + ((sel & 1) ? 16 : 0));
    }

    // copy descriptors: per chunk each matrix is 128 rows x 64 B = 512 x 16B;
    // 256 threads x 2 segs each. row = (tid>>2) + j*64, seg = (tid&3)*16.
    const int arow0 = tid >> 2;          // 0..63
    const int seg   = (tid & 3) * 16;
    const char* gA0 = (const char*)(A + (size_t)(bm + arow0) * lda + kbase) + seg;
    const size_t gAstep = (size_t)64 * lda * 2;     // +64 rows (bytes)
    const uint32_t dA0 = (uint32_t)(arow0 * 80 + seg);
    const char* gB[2];
    uint32_t dB[2];
    #pragma unroll
    for (int j = 0; j < 2; j++) {
        int r = arow0 + j * 64;
        int brow = bn + r; if (brow >= N) brow = N - 1;   // clamp; cols masked later
        gB[j] = (const char*)(B + (size_t)brow * ldb + kbase) + seg;
        dB[j] = (uint32_t)(HTILE_HALFS * 2 + r * 80 + seg);
    }

    float acc[4][4][4];
    #pragma unroll
    for (int i = 0; i < 4; i++)
        #pragma unroll
        for (int jj = 0; jj < 4; jj++)
            #pragma unroll
            for (int k = 0; k < 4; k++) acc[i][jj][k] = 0.f;

    const int NC = Klen / 32;

    // prologue: stage chunks 0 .. NSTAGE-2
    #pragma unroll
    for (int s = 0; s < NSTAGE - 1; s++) {
        if (s < NC) {
            uint32_t sb = sbase + (uint32_t)s * STAGE_BH;
            size_t off = (size_t)s * 64;
            #pragma unroll
            for (int j = 0; j < 2; j++) {
                CP_ASYNC16(sb + dA0 + j * (64 * 80), gA0 + j * gAstep + off);
                CP_ASYNC16(sb + dB[j], gB[j] + off);
            }
        }
        CP_COMMIT();
    }

    int cs = 0;
    for (int c = 0; c < NC; c++) {
        CP_WAIT1();
        __syncthreads();

        int nchunk = c + NSTAGE - 1;
        int is_ = cs + NSTAGE - 1; if (is_ >= NSTAGE) is_ -= NSTAGE;
        if (nchunk < NC) {
            uint32_t sb = sbase + (uint32_t)is_ * STAGE_BH;
            size_t off = (size_t)nchunk * 64;
            #pragma unroll
            for (int j = 0; j < 2; j++) {
                CP_ASYNC16(sb + dA0 + j * (64 * 80), gA0 + j * gAstep + off);
                CP_ASYNC16(sb + dB[j], gB[j] + off);
            }
        }
        CP_COMMIT();

        // compute chunk c: 2 k16-steps; B fragments loaded first (low live regs)
        const uint32_t stb = sbase + (uint32_t)cs * STAGE_BH;
        #pragma unroll
        for (int s = 0; s < 2; s++) {
            const uint32_t soff = (uint32_t)(s * 32);
            uint32_t bfr0[4], bfr1[4];
            ldsm4(bfr0, stb + boff[0] + soff);
            ldsm4(bfr1, stb + boff[1] + soff);
            // bfrX[0]=n0-7/k0-7, [1]=n0-7/k8-15, [2]=n8-15/k0-7, [3]=n8-15/k8-15
            #pragma unroll
            for (int fm = 0; fm < 4; fm++) {
                uint32_t af[4];
                ldsm4(af, stb + aoff[fm] + soff);
                mma_16n8k16(acc[fm][0], af, bfr0[0], bfr0[1]);
                mma_16n8k16(acc[fm][1], af, bfr0[2], bfr0[3]);
                mma_16n8k16(acc[fm][2], af, bfr1[0], bfr1[1]);
                mma_16n8k16(acc[fm][3], af, bfr1[2], bfr1[3]);
            }
        }
        cs++; if (cs == NSTAGE) cs = 0;
    }

    // writeback
    #pragma unroll
    for (int fm = 0; fm < 4; fm++) {
        int row0 = bm + wm * 64 + fm * 16 + g;
        #pragma unroll
        for (int fn = 0; fn < 4; fn++) {
            int col = bn + wn * 32 + fn * 8 + t * 2;
            if (col < N) {
                float* p0 = C + (size_t)row0 * ldc + col;
                float* p1 = C + (size_t)(row0 + 8) * ldc + col;
                if (MODE == 0) {
                    p0[0] = acc[fm][fn][0]; p0[1] = acc[fm][fn][1];
                    p1[0] = acc[fm][fn][2]; p1[1] = acc[fm][fn][3];
                } else {
                    atomicAdd(p0,     acc[fm][fn][0]);
                    atomicAdd(p0 + 1, acc[fm][fn][1]);
                    atomicAdd(p1,     acc[fm][fn][2]);
                    atomicAdd(p1 + 1, acc[fm][fn][3]);
                }
            }
        }
    }
}

// ---------------- fp32 -> fp16 conversion ----------------
__global__ void f2h_kernel(const float4* __restrict__ in, __half2* __restrict__ out, int n4) {
    int i = blockIdx.x * blockDim.x + threadIdx.x;
    if (i < n4) {
        float4 v = in[i];
        out[2 * i]     = __floats2half2_rn(v.x, v.y);
        out[2 * i + 1] = __floats2half2_rn(v.z, v.w);
    }
}

// ---------------- zero fill ----------------
__global__ void zero_kernel(float* __restrict__ p, int n) {
    int i = blockIdx.x * blockDim.x + threadIdx.x;
    if (i < n) p[i] = 0.f;
}

// ---------------- embed gather ----------------
__global__ void embed_kernel(const int* __restrict__ ids, const int* __restrict__ mask,
                             const float* __restrict__ embed, float* __restrict__ h) {
    int i = blockIdx.x * blockDim.x + threadIdx.x;
    if (i >= M_ROWS * DM) return;
    int row = i / DM, d = i % DM;
    float m = (float)mask[row];
    h[i] = embed[(size_t)ids[row] * DM + d] * m;
}

// ---------------- rmsnorm (emits fp16) ----------------
__global__ void rmsnorm_kernel(const float* __restrict__ x, const float* __restrict__ w,
                               __half* __restrict__ out) {
    int row = blockIdx.x;
    const float* xr = x + (size_t)row * DM;
    float s = 0.f;
    for (int d = threadIdx.x; d < DM; d += 256) { float v = xr[d]; s += v * v; }
    #pragma unroll
    for (int o = 16; o; o >>= 1) s += __shfl_xor_sync(0xffffffffu, s, o);
    __shared__ float sm[8];
    __shared__ float s_inv;
    if ((threadIdx.x & 31) == 0) sm[threadIdx.x >> 5] = s;
    __syncthreads();
    if (threadIdx.x == 0) {
        float tot = 0.f;
        #pragma unroll
        for (int i = 0; i < 8; i++) tot += sm[i];
        s_inv = rsqrtf(tot / (float)DM + 1e-5f);
    }
    __syncthreads();
    float inv = s_inv;
    for (int d = threadIdx.x; d < DM; d += 256)
        out[(size_t)row * DM + d] = __float2half_rn(xr[d] * inv * w[d]);
}

// ---------------- fp32 SGEMM NT + fused bias/softplus (dt_proj, K=48) --------
__global__ void __launch_bounds__(256)
sgemm_nt_softplus(const float* __restrict__ A, const float* __restrict__ B,
                  float* __restrict__ C, const float* __restrict__ bias,
                  int M, int N, int Kdim, int lda, int ldb, int ldc) {
    __shared__ float As[16][128];
    __shared__ float Bs[16][64 + 4];
    int bm = blockIdx.y * 128;
    int bn = blockIdx.x * 64;
    int tid = threadIdx.x;
    int tx = tid & 15;
    int ty = tid >> 4;
    float acc[8][4];
    #pragma unroll
    for (int i = 0; i < 8; i++)
        #pragma unroll
        for (int j = 0; j < 4; j++) acc[i][j] = 0.f;

    for (int k0 = 0; k0 < Kdim; k0 += 16) {
        #pragma unroll
        for (int it = 0; it < 2; it++) {
            int i = tid + it * 256;
            int r = i >> 2, c4 = (i & 3) * 4;
            float4 v = *(const float4*)(A + (size_t)(bm + r) * lda + k0 + c4);
            As[c4 + 0][r] = v.x; As[c4 + 1][r] = v.y;
            As[c4 + 2][r] = v.z; As[c4 + 3][r] = v.w;
        }
        {
            int r = tid >> 2, c4 = (tid & 3) * 4;
            float4 v = make_float4(0.f, 0.f, 0.f, 0.f);
            if (bn + r < N)
                v = *(const float4*)(B + (size_t)(bn + r) * ldb + k0 + c4);
            Bs[c4 + 0][r] = v.x; Bs[c4 + 1][r] = v.y;
            Bs[c4 + 2][r] = v.z; Bs[c4 + 3][r] = v.w;
        }
        __syncthreads();
        #pragma unroll
        for (int c = 0; c < 16; c++) {
            float ra[8], rb[4];
            #pragma unroll
            for (int i = 0; i < 8; i++) ra[i] = As[c][ty * 8 + i];
            #pragma unroll
            for (int j = 0; j < 4; j++) rb[j] = Bs[c][tx * 4 + j];
            #pragma unroll
            for (int i = 0; i < 8; i++)
                #pragma unroll
                for (int j = 0; j < 4; j++)
                    acc[i][j] += ra[i] * rb[j];
        }
        __syncthreads();
    }

    #pragma unroll
    for (int i = 0; i < 8; i++) {
        int row = bm + ty * 8 + i;
        #pragma unroll
        for (int j = 0; j < 4; j++) {
            int col = bn + tx * 4 + j;
            if (col < N) {
                float v = acc[i][j] + bias[col];
                C[(size_t)row * ldc + col] = (v > 20.f) ? v : log1pf(__expf(v));
            }
        }
    }
}

// ---------------- depthwise causal conv (K=4) + SiLU (emits fp16) ------------
__global__ void conv_silu_kernel(const float* __restrict__ xz, const float* __restrict__ cw,
                                 const float* __restrict__ cb, __half* __restrict__ xc) {
    int i = blockIdx.x * blockDim.x + threadIdx.x;
    if (i >= M_ROWS * DI) return;
    int row = i / DI, d = i % DI;
    int b = row / L_SEQ, l = row % L_SEQ;
    float acc = cb[d];
    #pragma unroll
    for (int k = 0; k < KCONV; k++) {
        int ll = l - (KCONV - 1) + k;
        if (ll >= 0)
            acc += cw[d * KCONV + k] * xz[(size_t)(b * L_SEQ + ll) * (2 * DI) + d];
    }
    xc[i] = __float2half_rn(acc / (1.f + __expf(-acc)));
}

// ---------------- SSM scan (unroll-4 prefetch) ----------------
__global__ void scan_kernel(const float* __restrict__ dt, const __half* __restrict__ xc,
                            const float* __restrict__ proj, const float* __restrict__ xz,
                            const float* __restrict__ A_log, const float* __restrict__ Dp,
                            __half* __restrict__ y) {
    int gid = (blockIdx.x * blockDim.x + threadIdx.x) >> 4;
    int n = threadIdx.x & 15;
    if (gid >= BATCH * DI) return;
    int b = gid / DI, d = gid % DI;
    float A = -__expf(A_log[d * NSTATE + n]);
    float Dval = Dp[d];
    float h = 0.f;

    const size_t row0 = (size_t)b * L_SEQ;
    float cdt[4], cxv[4], cBv[4], cCv[4];
    float ndt[4], nxv[4], nBv[4], nCv[4];

    #pragma unroll
    for (int j = 0; j < 4; j++) {
        size_t rr = row0 + j;
        cdt[j] = dt[rr * DI + d];
        cxv[j] = __half2float(xc[rr * DI + d]);
        cBv[j] = proj[rr * PROJ_N + RRANK + n];
        cCv[j] = proj[rr * PROJ_N + RRANK + NSTATE + n];
    }

    const int NB = L_SEQ / 4;
    for (int lb = 0; lb < NB; lb++) {
        if (lb + 1 < NB) {
            #pragma unroll
            for (int j = 0; j < 4; j++) {
                size_t rr = row0 + (lb + 1) * 4 + j;
                ndt[j] = dt[rr * DI + d];
                nxv[j] = __half2float(xc[rr * DI + d]);
                nBv[j] = proj[rr * PROJ_N + RRANK + n];
                nCv[j] = proj[rr * PROJ_N + RRANK + NSTATE + n];
            }
        }
        #pragma unroll
        for (int j = 0; j < 4; j++) {
            size_t row = row0 + lb * 4 + j;
            h = __expf(cdt[j] * A) * h + cdt[j] * cBv[j] * cxv[j];
            float p = h * cCv[j];
            p += __shfl_xor_sync(0xffffffffu, p, 1);
            p += __shfl_xor_sync(0xffffffffu, p, 2);
            p += __shfl_xor_sync(0xffffffffu, p, 4);
            p += __shfl_xor_sync(0xffffffffu, p, 8);
            if (n == 0) {
                float zv = xz[row * (2 * DI) + DI + d];
                float yv = p + Dval * cxv[j];
                y[row * DI + d] = __float2half_rn(yv * (zv / (1.f + __expf(-zv))));
            }
        }
        #pragma unroll
        for (int j = 0; j < 4; j++) {
            cdt[j] = ndt[j]; cxv[j] = nxv[j]; cBv[j] = nBv[j]; cCv[j] = nCv[j];
        }
    }
}

// ---------------- host orchestration ----------------
static inline void conv_f2h(const float* src, __half* dst, size_t n) {
    int n4 = (int)(n / 4);
    f2h_kernel<<<(n4 + 255) / 256, 256>>>((const float4*)src, (__half2*)dst, n4);
}

extern "C" void kernel_launch(void* const* d_in, const int* in_sizes, int n_in,
                              void* d_out, int out_size) {
    const int*   q_ids   = (const int*)d_in[0];
    const int*   q_mask  = (const int*)d_in[1];
    const float* embed   = (const float*)d_in[4];
    const float* in_w    = (const float*)d_in[5];
    const float* conv_w  = (const float*)d_in[6];
    const float* conv_b  = (const float*)d_in[7];
    const float* x_w     = (const float*)d_in[8];
    const float* dt_w    = (const float*)d_in[9];
    const float* dt_b    = (const float*)d_in[10];
    const float* A_log   = (const float*)d_in[11];
    const float* Dp      = (const float*)d_in[12];
    const float* out_w   = (const float*)d_in[13];
    const float* norm_w  = (const float*)d_in[14];
    const float* fnorm_w = (const float*)d_in[15];
    float* out = (float*)d_out;

    cudaFuncSetAttribute(h16_gemm_nt<0>, cudaFuncAttributeMaxDynamicSharedMemorySize, HMMA_SMEM);
    cudaFuncSetAttribute(h16_gemm_nt<2>, cudaFuncAttributeMaxDynamicSharedMemorySize, HMMA_SMEM);

    float *h, *xz, *proj, *dt;
    __half *r_h, *xc_h, *y_h, *emb_h, *inw_h, *xw_h, *outw_h;
    cudaGetSymbolAddress((void**)&h,    g_h);
    cudaGetSymbolAddress((void**)&xz,   g_xz);
    cudaGetSymbolAddress((void**)&proj, g_proj);
    cudaGetSymbolAddress((void**)&dt,   g_dt);
    cudaGetSymbolAddress((void**)&r_h,  g_r_h);
    cudaGetSymbolAddress((void**)&xc_h, g_xc_h);
    cudaGetSymbolAddress((void**)&y_h,  g_y_h);
    cudaGetSymbolAddress((void**)&emb_h,  g_emb_h);
    cudaGetSymbolAddress((void**)&inw_h,  g_inw_h);
    cudaGetSymbolAddress((void**)&xw_h,   g_xw_h);
    cudaGetSymbolAddress((void**)&outw_h, g_outw_h);

    // Launch order: ncu profiles OUR launch #4 (harness adds 2 before; -s 5 -c 1)
    conv_f2h(in_w, inw_h, (size_t)NLAYER * 2 * DI * DM);                        // 1
    embed_kernel<<<(M_ROWS * DM + 255) / 256, 256>>>(q_ids, q_mask, embed, h);  // 2

    for (int l = 0; l < NLAYER; l++) {
        const __half* inw_l  = inw_h  + (size_t)l * (2 * DI) * DM;
        const __half* xw_l   = xw_h   + (size_t)l * PROJ_N * DI;
        const __half* outw_l = outw_h + (size_t)l * DM * DI;
        const float* cw_l    = conv_w + (size_t)l * DI * KCONV;
        const float* cb_l    = conv_b + (size_t)l * DI;
        const float* dt_w_l  = dt_w  + (size_t)l * DI * RRANK;
        const float* dt_b_l  = dt_b  + (size_t)l * DI;
        const float* A_log_l = A_log + (size_t)l * DI * NSTATE;
        const float* Dp_l    = Dp    + (size_t)l * DI;
        const float* norm_l  = norm_w + (size_t)l * DM;

        rmsnorm_kernel<<<M_ROWS, 256>>>(h, norm_l, r_h);                        // 3 (l=0)

        // xz = r @ in_w^T  (1024 x 3072, K=768)                                // 4 (l=0) <- ncu
        h16_gemm_nt<0><<<dim3(M_ROWS / 128, (2 * DI) / 128, 1), 256, HMMA_SMEM>>>(
            r_h, inw_l, xz, 2 * DI, DM, DM, DM, 2 * DI);

        if (l == 0) {
            conv_f2h(x_w,   xw_h,  (size_t)NLAYER * PROJ_N * DI);
            conv_f2h(out_w, outw_h,(size_t)NLAYER * DM * DI);
        }

        conv_silu_kernel<<<(M_ROWS * DI + 255) / 256, 256>>>(xz, cw_l, cb_l, xc_h);

        // proj = xc @ x_w^T  (1024 x 80, K=1536) — split-K x8, atomic
        zero_kernel<<<(M_ROWS * PROJ_N + 255) / 256, 256>>>(proj, M_ROWS * PROJ_N);
        h16_gemm_nt<2><<<dim3(M_ROWS / 128, 1, 8), 256, HMMA_SMEM>>>(
            xc_h, xw_l, proj, PROJ_N, DI / 8, DI, DI, PROJ_N);

        // dt = softplus(proj[:, :48] @ dt_w^T + dt_b)  (1024 x 1536, K=48)
        sgemm_nt_softplus<<<dim3((DI + 63) / 64, M_ROWS / 128), 256>>>(
            proj, dt_w_l, dt, dt_b_l, M_ROWS, DI, RRANK, PROJ_N, RRANK, DI);

        scan_kernel<<<(BATCH * DI * 16 + 255) / 256, 256>>>(
            dt, xc_h, proj, xz, A_log_l, Dp_l, y_h);

        // h += y @ out_w^T  (1024 x 768, K=1536) — split-K x4, atomic into residual
        h16_gemm_nt<2><<<dim3(M_ROWS / 128, DM / 128, 4), 256, HMMA_SMEM>>>(
            y_h, outw_l, h, DM, DI / 4, DI, DI, DM);
    }

    conv_f2h(embed, emb_h, (size_t)VOCAB * DM);

    rmsnorm_kernel<<<M_ROWS, 256>>>(h, fnorm_w, r_h);

    // logits = r @ embed^T  (1024 x 50280, K=768)
    h16_gemm_nt<0><<<dim3(M_ROWS / 128, (VOCAB + 127) / 128, 1), 256, HMMA_SMEM>>>(
        r_h, emb_h, out, VOCAB, DM, DM, DM, VOCAB);
}

// round 15
// speedup vs baseline: 1.1571x; 1.1571x over previous
#include <cuda_runtime.h>
#include <cuda_fp16.h>
#include <math.h>
#include <stdint.h>

// ---------------- problem constants ----------------
#define BATCH   2
#define L_SEQ   512
#define DM      768
#define DI      1536
#define NSTATE  16
#define RRANK   48
#define KCONV   4
#define NLAYER  4
#define VOCAB   50280
#define M_ROWS  (BATCH * L_SEQ)        // 1024
#define PROJ_N  (RRANK + 2 * NSTATE)   // 80
#define DTK     64                      // padded K for dt_proj

// ---------------- scratch (device globals) ----------------
__device__ float g_h   [M_ROWS * DM];
__device__ float g_xz  [M_ROWS * 2 * DI];
__device__ float g_proj[M_ROWS * PROJ_N];
__device__ float g_dt  [M_ROWS * DI];
__device__ __half g_r_h [M_ROWS * DM];
__device__ __half g_xc_h[M_ROWS * DI];
__device__ __half g_y_h [M_ROWS * DI];
__device__ __half g_proj_h[M_ROWS * PROJ_N];
__device__ __half g_emb_h [VOCAB * DM];
__device__ __half g_inw_h [NLAYER * 2 * DI * DM];
__device__ __half g_xw_h  [NLAYER * PROJ_N * DI];
__device__ __half g_outw_h[NLAYER * DM * DI];
__device__ __half g_dtw_h [NLAYER * DI * DTK];   // zero-padded cols 48..63

// ---------------- PTX helpers (family-common) ----------------
__device__ __forceinline__ uint32_t smem_u32(const void* p) {
    uint32_t a;
    asm("{ .reg .u64 t; cvta.to.shared.u64 t, %1; cvt.u32.u64 %0, t; }"
        : "=r"(a) : "l"(p));
    return a;
}
__device__ __forceinline__ void ldsm4(uint32_t* r, uint32_t addr) {
    asm volatile("ldmatrix.sync.aligned.m8n8.x4.shared.b16 {%0,%1,%2,%3}, [%4];"
        : "=r"(r[0]), "=r"(r[1]), "=r"(r[2]), "=r"(r[3]) : "r"(addr));
}
__device__ __forceinline__ void mma_16n8k16(float* d, const uint32_t* a, const uint32_t* b) {
    asm volatile(
        "mma.sync.aligned.m16n8k16.row.col.f32.f16.f16.f32 "
        "{%0,%1,%2,%3}, {%4,%5,%6,%7}, {%8,%9}, {%0,%1,%2,%3};"
        : "+f"(d[0]), "+f"(d[1]), "+f"(d[2]), "+f"(d[3])
        : "r"(a[0]), "r"(a[1]), "r"(a[2]), "r"(a[3]), "r"(b[0]), "r"(b[1]));
}
#define CP_ASYNC16(dst, src) \
    asm volatile("cp.async.cg.shared.global [%0], [%1], 16;" :: "r"(dst), "l"(src))
#define CP_COMMIT() asm volatile("cp.async.commit_group;" ::: "memory")
#define CP_WAIT2()  asm volatile("cp.async.wait_group 2;" ::: "memory")

// ======== fp16 mma.sync GEMM NT: C[M,N] (op)= A[M,K] * B[N,K]^T, fp32 accum ==
// Block tile 128x128, BK=32 halfs, 256 threads (8 warps, 2M x 4N, warp 64x32).
// 4-stage cp.async with wait_group 2. Row stride 40 halfs (80 B).
// M % 128 == 0, Klen % 32 == 0. blockIdx.z = K-split.
// MODE: 0 store, 2 atomicAdd, 3 store softplus(acc + bias[col]).
#define HSTRIDE 40
#define HTILE_HALFS (128 * HSTRIDE)          // 5120 halfs per matrix tile
#define STAGE_BH (2 * HTILE_HALFS * 2)       // 20480 B per stage
#define NSTAGE  4
#define HMMA_SMEM (NSTAGE * STAGE_BH)        // 81920 B

template <int MODE>
__global__ void __launch_bounds__(256)
h16_gemm_nt(const __half* __restrict__ A, const __half* __restrict__ B,
            float* __restrict__ C, int N, int Klen, int lda, int ldb, int ldc,
            const float* __restrict__ bias) {
    extern __shared__ uint32_t smem[];
    const int tid = threadIdx.x;
    const int wid = tid >> 5;
    const int lane = tid & 31;
    const int g = lane >> 2;
    const int t = lane & 3;
    const int wm = wid & 1;      // warp M index (2) -> 64 rows
    const int wn = wid >> 1;     // warp N index (4) -> 32 cols
    const int bm = blockIdx.x * 128;
    const int bn = blockIdx.y * 128;
    const int kbase = blockIdx.z * Klen;

    const uint32_t sbase = smem_u32(smem);

    // per-lane ldmatrix offsets (bytes from stage base)
    const int j8  = lane & 7;
    const int sel = lane >> 3;
    uint32_t aoff[4], boff[2];
    #pragma unroll
    for (int fm = 0; fm < 4; fm++) {
        int row = wm * 64 + fm * 16 + j8 + ((sel & 1) << 3);
        aoff[fm] = (uint32_t)(row * 80 + ((sel & 2) ? 16 : 0));
    }
    #pragma unroll
    for (int p = 0; p < 2; p++) {
        int row = wn * 32 + p * 16 + j8 + ((sel & 2) ? 8 : 0);
        boff[p] = (uint32_t)(HTILE_HALFS * 2 + row * 80 + ((sel & 1) ? 16 : 0));
    }

    // copy descriptors: per chunk each matrix is 128 rows x 64 B = 512 x 16B;
    // 256 threads x 2 segs each. row = (tid>>2) + j*64, seg = (tid&3)*16.
    const int arow0 = tid >> 2;          // 0..63
    const int seg   = (tid & 3) * 16;
    const char* gA0 = (const char*)(A + (size_t)(bm + arow0) * lda + kbase) + seg;
    const size_t gAstep = (size_t)64 * lda * 2;     // +64 rows (bytes)
    const uint32_t dA0 = (uint32_t)(arow0 * 80 + seg);
    const char* gB[2];
    uint32_t dB[2];
    #pragma unroll
    for (int j = 0; j < 2; j++) {
        int r = arow0 + j * 64;
        int brow = bn + r; if (brow >= N) brow = N - 1;   // clamp; cols masked later
        gB[j] = (const char*)(B + (size_t)brow * ldb + kbase) + seg;
        dB[j] = (uint32_t)(HTILE_HALFS * 2 + r * 80 + seg);
    }

    float acc[4][4][4];
    #pragma unroll
    for (int i = 0; i < 4; i++)
        #pragma unroll
        for (int jj = 0; jj < 4; jj++)
            #pragma unroll
            for (int k = 0; k < 4; k++) acc[i][jj][k] = 0.f;

    const int NC = Klen / 32;

    // prologue: stage chunks 0 .. NSTAGE-2 (3 chunks outstanding entering loop)
    #pragma unroll
    for (int s = 0; s < NSTAGE - 1; s++) {
        if (s < NC) {
            uint32_t sb = sbase + (uint32_t)s * STAGE_BH;
            size_t off = (size_t)s * 64;
            #pragma unroll
            for (int j = 0; j < 2; j++) {
                CP_ASYNC16(sb + dA0 + j * (64 * 80), gA0 + j * gAstep + off);
                CP_ASYNC16(sb + dB[j], gB[j] + off);
            }
        }
        CP_COMMIT();
    }

    int cs = 0;
    for (int c = 0; c < NC; c++) {
        CP_WAIT2();
        __syncthreads();

        int nchunk = c + NSTAGE - 1;
        int is_ = cs + NSTAGE - 1; if (is_ >= NSTAGE) is_ -= NSTAGE;
        if (nchunk < NC) {
            uint32_t sb = sbase + (uint32_t)is_ * STAGE_BH;
            size_t off = (size_t)nchunk * 64;
            #pragma unroll
            for (int j = 0; j < 2; j++) {
                CP_ASYNC16(sb + dA0 + j * (64 * 80), gA0 + j * gAstep + off);
                CP_ASYNC16(sb + dB[j], gB[j] + off);
            }
        }
        CP_COMMIT();

        // compute chunk c: 2 k16-steps
        const uint32_t stb = sbase + (uint32_t)cs * STAGE_BH;
        #pragma unroll
        for (int s = 0; s < 2; s++) {
            const uint32_t soff = (uint32_t)(s * 32);
            uint32_t af[4][4];
            #pragma unroll
            for (int fm = 0; fm < 4; fm++)
                ldsm4(af[fm], stb + aoff[fm] + soff);
            #pragma unroll
            for (int p = 0; p < 2; p++) {
                uint32_t bfr[4];
                ldsm4(bfr, stb + boff[p] + soff);
                // bfr[0]=n0-7/k0-7, bfr[1]=n0-7/k8-15, bfr[2]=n8-15/k0-7, bfr[3]=n8-15/k8-15
                uint32_t b0[2] = { bfr[0], bfr[1] };
                uint32_t b1[2] = { bfr[2], bfr[3] };
                #pragma unroll
                for (int fm = 0; fm < 4; fm++) {
                    mma_16n8k16(acc[fm][2 * p],     af[fm], b0);
                    mma_16n8k16(acc[fm][2 * p + 1], af[fm], b1);
                }
            }
        }
        cs++; if (cs == NSTAGE) cs = 0;
    }

    // writeback
    #pragma unroll
    for (int fm = 0; fm < 4; fm++) {
        int row0 = bm + wm * 64 + fm * 16 + g;
        #pragma unroll
        for (int fn = 0; fn < 4; fn++) {
            int col = bn + wn * 32 + fn * 8 + t * 2;
            if (col < N) {
                float* p0 = C + (size_t)row0 * ldc + col;
                float* p1 = C + (size_t)(row0 + 8) * ldc + col;
                if (MODE == 0) {
                    p0[0] = acc[fm][fn][0]; p0[1] = acc[fm][fn][1];
                    p1[0] = acc[fm][fn][2]; p1[1] = acc[fm][fn][3];
                } else if (MODE == 2) {
                    atomicAdd(p0,     acc[fm][fn][0]);
                    atomicAdd(p0 + 1, acc[fm][fn][1]);
                    atomicAdd(p1,     acc[fm][fn][2]);
                    atomicAdd(p1 + 1, acc[fm][fn][3]);
                } else {  // MODE 3: bias + softplus
                    float b0v = bias[col], b1v = bias[col + 1];
                    float v;
                    v = acc[fm][fn][0] + b0v; p0[0] = (v > 20.f) ? v : log1pf(__expf(v));
                    v = acc[fm][fn][1] + b1v; p0[1] = (v > 20.f) ? v : log1pf(__expf(v));
                    v = acc[fm][fn][2] + b0v; p1[0] = (v > 20.f) ? v : log1pf(__expf(v));
                    v = acc[fm][fn][3] + b1v; p1[1] = (v > 20.f) ? v : log1pf(__expf(v));
                }
            }
        }
    }
}

// ---------------- fp32 -> fp16 conversion ----------------
__global__ void f2h_kernel(const float4* __restrict__ in, __half2* __restrict__ out, int n4) {
    int i = blockIdx.x * blockDim.x + threadIdx.x;
    if (i < n4) {
        float4 v = in[i];
        out[2 * i]     = __floats2half2_rn(v.x, v.y);
        out[2 * i + 1] = __floats2half2_rn(v.z, v.w);
    }
}

// ---------------- dt_w pad+convert: [DI,48] fp32 -> [DI,64] fp16 (zeros 48+) --
__global__ void dtw_pad_kernel(const float* __restrict__ dtw, __half* __restrict__ out) {
    int i = blockIdx.x * blockDim.x + threadIdx.x;
    if (i >= NLAYER * DI * DTK) return;
    int col = i % DTK;
    int rowl = i / DTK;            // layer*DI + row
    out[i] = (col < RRANK) ? __float2half_rn(dtw[rowl * RRANK + col]) : __ushort_as_half(0);
}

// ---------------- zero fill ----------------
__global__ void zero_kernel(float* __restrict__ p, int n) {
    int i = blockIdx.x * blockDim.x + threadIdx.x;
    if (i < n) p[i] = 0.f;
}

// ---------------- embed gather ----------------
__global__ void embed_kernel(const int* __restrict__ ids, const int* __restrict__ mask,
                             const float* __restrict__ embed, float* __restrict__ h) {
    int i = blockIdx.x * blockDim.x + threadIdx.x;
    if (i >= M_ROWS * DM) return;
    int row = i / DM, d = i % DM;
    float m = (float)mask[row];
    h[i] = embed[(size_t)ids[row] * DM + d] * m;
}

// ---------------- rmsnorm (emits fp16) ----------------
__global__ void rmsnorm_kernel(const float* __restrict__ x, const float* __restrict__ w,
                               __half* __restrict__ out) {
    int row = blockIdx.x;
    const float* xr = x + (size_t)row * DM;
    float s = 0.f;
    for (int d = threadIdx.x; d < DM; d += 256) { float v = xr[d]; s += v * v; }
    #pragma unroll
    for (int o = 16; o; o >>= 1) s += __shfl_xor_sync(0xffffffffu, s, o);
    __shared__ float sm[8];
    __shared__ float s_inv;
    if ((threadIdx.x & 31) == 0) sm[threadIdx.x >> 5] = s;
    __syncthreads();
    if (threadIdx.x == 0) {
        float tot = 0.f;
        #pragma unroll
        for (int i = 0; i < 8; i++) tot += sm[i];
        s_inv = rsqrtf(tot / (float)DM + 1e-5f);
    }
    __syncthreads();
    float inv = s_inv;
    for (int d = threadIdx.x; d < DM; d += 256)
        out[(size_t)row * DM + d] = __float2half_rn(xr[d] * inv * w[d]);
}

// ---------------- depthwise causal conv (K=4) + SiLU (emits fp16) ------------
__global__ void conv_silu_kernel(const float* __restrict__ xz, const float* __restrict__ cw,
                                 const float* __restrict__ cb, __half* __restrict__ xc) {
    int i = blockIdx.x * blockDim.x + threadIdx.x;
    if (i >= M_ROWS * DI) return;
    int row = i / DI, d = i % DI;
    int b = row / L_SEQ, l = row % L_SEQ;
    float acc = cb[d];
    #pragma unroll
    for (int k = 0; k < KCONV; k++) {
        int ll = l - (KCONV - 1) + k;
        if (ll >= 0)
            acc += cw[d * KCONV + k] * xz[(size_t)(b * L_SEQ + ll) * (2 * DI) + d];
    }
    xc[i] = __float2half_rn(acc / (1.f + __expf(-acc)));
}

// ---------------- proj fp32 -> fp16 ----------------
__global__ void proj_f2h_kernel(const float* __restrict__ in, __half* __restrict__ out) {
    int i = blockIdx.x * blockDim.x + threadIdx.x;
    if (i < M_ROWS * PROJ_N) out[i] = __float2half_rn(in[i]);
}

// ---------------- SSM scan (unroll-4 prefetch) ----------------
__global__ void scan_kernel(const float* __restrict__ dt, const __half* __restrict__ xc,
                            const float* __restrict__ proj, const float* __restrict__ xz,
                            const float* __restrict__ A_log, const float* __restrict__ Dp,
                            __half* __restrict__ y) {
    int gid = (blockIdx.x * blockDim.x + threadIdx.x) >> 4;
    int n = threadIdx.x & 15;
    if (gid >= BATCH * DI) return;
    int b = gid / DI, d = gid % DI;
    float A = -__expf(A_log[d * NSTATE + n]);
    float Dval = Dp[d];
    float h = 0.f;

    const size_t row0 = (size_t)b * L_SEQ;
    float cdt[4], cxv[4], cBv[4], cCv[4];
    float ndt[4], nxv[4], nBv[4], nCv[4];

    #pragma unroll
    for (int j = 0; j < 4; j++) {
        size_t rr = row0 + j;
        cdt[j] = dt[rr * DI + d];
        cxv[j] = __half2float(xc[rr * DI + d]);
        cBv[j] = proj[rr * PROJ_N + RRANK + n];
        cCv[j] = proj[rr * PROJ_N + RRANK + NSTATE + n];
    }

    const int NB = L_SEQ / 4;
    for (int lb = 0; lb < NB; lb++) {
        if (lb + 1 < NB) {
            #pragma unroll
            for (int j = 0; j < 4; j++) {
                size_t rr = row0 + (lb + 1) * 4 + j;
                ndt[j] = dt[rr * DI + d];
                nxv[j] = __half2float(xc[rr * DI + d]);
                nBv[j] = proj[rr * PROJ_N + RRANK + n];
                nCv[j] = proj[rr * PROJ_N + RRANK + NSTATE + n];
            }
        }
        #pragma unroll
        for (int j = 0; j < 4; j++) {
            size_t row = row0 + lb * 4 + j;
            h = __expf(cdt[j] * A) * h + cdt[j] * cBv[j] * cxv[j];
            float p = h * cCv[j];
            p += __shfl_xor_sync(0xffffffffu, p, 1);
            p += __shfl_xor_sync(0xffffffffu, p, 2);
            p += __shfl_xor_sync(0xffffffffu, p, 4);
            p += __shfl_xor_sync(0xffffffffu, p, 8);
            if (n == 0) {
                float zv = xz[row * (2 * DI) + DI + d];
                float yv = p + Dval * cxv[j];
                y[row * DI + d] = __float2half_rn(yv * (zv / (1.f + __expf(-zv))));
            }
        }
        #pragma unroll
        for (int j = 0; j < 4; j++) {
            cdt[j] = ndt[j]; cxv[j] = nxv[j]; cBv[j] = nBv[j]; cCv[j] = nCv[j];
        }
    }
}

// ---------------- host orchestration ----------------
static inline void conv_f2h(const float* src, __half* dst, size_t n) {
    int n4 = (int)(n / 4);
    f2h_kernel<<<(n4 + 255) / 256, 256>>>((const float4*)src, (__half2*)dst, n4);
}

extern "C" void kernel_launch(void* const* d_in, const int* in_sizes, int n_in,
                              void* d_out, int out_size) {
    const int*   q_ids   = (const int*)d_in[0];
    const int*   q_mask  = (const int*)d_in[1];
    const float* embed   = (const float*)d_in[4];
    const float* in_w    = (const float*)d_in[5];
    const float* conv_w  = (const float*)d_in[6];
    const float* conv_b  = (const float*)d_in[7];
    const float* x_w     = (const float*)d_in[8];
    const float* dt_w    = (const float*)d_in[9];
    const float* dt_b    = (const float*)d_in[10];
    const float* A_log   = (const float*)d_in[11];
    const float* Dp      = (const float*)d_in[12];
    const float* out_w   = (const float*)d_in[13];
    const float* norm_w  = (const float*)d_in[14];
    const float* fnorm_w = (const float*)d_in[15];
    float* out = (float*)d_out;

    cudaFuncSetAttribute(h16_gemm_nt<0>, cudaFuncAttributeMaxDynamicSharedMemorySize, HMMA_SMEM);
    cudaFuncSetAttribute(h16_gemm_nt<2>, cudaFuncAttributeMaxDynamicSharedMemorySize, HMMA_SMEM);
    cudaFuncSetAttribute(h16_gemm_nt<3>, cudaFuncAttributeMaxDynamicSharedMemorySize, HMMA_SMEM);

    float *h, *xz, *proj, *dt;
    __half *r_h, *xc_h, *y_h, *proj_h, *emb_h, *inw_h, *xw_h, *outw_h, *dtw_h;
    cudaGetSymbolAddress((void**)&h,    g_h);
    cudaGetSymbolAddress((void**)&xz,   g_xz);
    cudaGetSymbolAddress((void**)&proj, g_proj);
    cudaGetSymbolAddress((void**)&dt,   g_dt);
    cudaGetSymbolAddress((void**)&r_h,  g_r_h);
    cudaGetSymbolAddress((void**)&xc_h, g_xc_h);
    cudaGetSymbolAddress((void**)&y_h,  g_y_h);
    cudaGetSymbolAddress((void**)&proj_h, g_proj_h);
    cudaGetSymbolAddress((void**)&emb_h,  g_emb_h);
    cudaGetSymbolAddress((void**)&inw_h,  g_inw_h);
    cudaGetSymbolAddress((void**)&xw_h,   g_xw_h);
    cudaGetSymbolAddress((void**)&outw_h, g_outw_h);
    cudaGetSymbolAddress((void**)&dtw_h,  g_dtw_h);

    // Launch order: ncu profiles OUR launch #4 (harness adds 2 before; -s 5 -c 1)
    conv_f2h(in_w, inw_h, (size_t)NLAYER * 2 * DI * DM);                        // 1
    embed_kernel<<<(M_ROWS * DM + 255) / 256, 256>>>(q_ids, q_mask, embed, h);  // 2

    for (int l = 0; l < NLAYER; l++) {
        const __half* inw_l  = inw_h  + (size_t)l * (2 * DI) * DM;
        const __half* xw_l   = xw_h   + (size_t)l * PROJ_N * DI;
        const __half* outw_l = outw_h + (size_t)l * DM * DI;
        const __half* dtw_l  = dtw_h  + (size_t)l * DI * DTK;
        const float* cw_l    = conv_w + (size_t)l * DI * KCONV;
        const float* cb_l    = conv_b + (size_t)l * DI;
        const float* dt_b_l  = dt_b  + (size_t)l * DI;
        const float* A_log_l = A_log + (size_t)l * DI * NSTATE;
        const float* Dp_l    = Dp    + (size_t)l * DI;
        const float* norm_l  = norm_w + (size_t)l * DM;

        rmsnorm_kernel<<<M_ROWS, 256>>>(h, norm_l, r_h);                        // 3 (l=0)

        // xz = r @ in_w^T  (1024 x 3072, K=768)                                // 4 (l=0) <- ncu
        h16_gemm_nt<0><<<dim3(M_ROWS / 128, (2 * DI) / 128, 1), 256, HMMA_SMEM>>>(
            r_h, inw_l, xz, 2 * DI, DM, DM, DM, 2 * DI, nullptr);

        if (l == 0) {
            conv_f2h(x_w,   xw_h,  (size_t)NLAYER * PROJ_N * DI);
            conv_f2h(out_w, outw_h,(size_t)NLAYER * DM * DI);
            dtw_pad_kernel<<<(NLAYER * DI * DTK + 255) / 256, 256>>>(dt_w, dtw_h);
        }

        conv_silu_kernel<<<(M_ROWS * DI + 255) / 256, 256>>>(xz, cw_l, cb_l, xc_h);

        // proj = xc @ x_w^T  (1024 x 80, K=1536) — split-K x8, atomic
        zero_kernel<<<(M_ROWS * PROJ_N + 255) / 256, 256>>>(proj, M_ROWS * PROJ_N);
        h16_gemm_nt<2><<<dim3(M_ROWS / 128, 1, 8), 256, HMMA_SMEM>>>(
            xc_h, xw_l, proj, PROJ_N, DI / 8, DI, DI, PROJ_N, nullptr);

        // proj -> fp16 for dt GEMM
        proj_f2h_kernel<<<(M_ROWS * PROJ_N + 255) / 256, 256>>>(proj, proj_h);

        // dt = softplus(proj_h[:, :64] @ dtw_pad^T + dt_b)  (1024 x 1536, K=64)
        h16_gemm_nt<3><<<dim3(M_ROWS / 128, DI / 128, 1), 256, HMMA_SMEM>>>(
            proj_h, dtw_l, dt, DI, DTK, PROJ_N, DTK, DI, dt_b_l);

        scan_kernel<<<(BATCH * DI * 16 + 255) / 256, 256>>>(
            dt, xc_h, proj, xz, A_log_l, Dp_l, y_h);

        // h += y @ out_w^T  (1024 x 768, K=1536) — split-K x4, atomic into residual
        h16_gemm_nt<2><<<dim3(M_ROWS / 128, DM / 128, 4), 256, HMMA_SMEM>>>(
            y_h, outw_l, h, DM, DI / 4, DI, DI, DM, nullptr);
    }

    conv_f2h(embed, emb_h, (size_t)VOCAB * DM);

    rmsnorm_kernel<<<M_ROWS, 256>>>(h, fnorm_w, r_h);

    // logits = r @ embed^T  (1024 x 50280, K=768)
    h16_gemm_nt<0><<<dim3(M_ROWS / 128, (VOCAB + 127) / 128, 1), 256, HMMA_SMEM>>>(
        r_h, emb_h, out, VOCAB, DM, DM, DM, VOCAB, nullptr);
}